// round 4
// baseline (speedup 1.0000x reference)
#include <cuda_runtime.h>
#include <math.h>
#include <stdint.h>

#define N_ATOMS 10000
#define N_PAIRS 320000
#define CC 64
#define NB 10

// ---------------- scratch (static device globals; no runtime alloc) ----------
__device__ __align__(16) float g_A[N_ATOMS * 640];        // p1_in @ pi_W[0:64]
__device__ __align__(16) float g_B[N_ATOMS * 640];        // p1_in @ pi_W[64:128]
__device__ __align__(16) float g_v[N_ATOMS * 4];          // padded (use 3)
__device__ __align__(16) float g_p1scat[N_ATOMS * 128];
__device__ __align__(16) float g_p3acc[N_ATOMS * 192];

// ---------------- helpers ----------------------------------------------------
__device__ __forceinline__ float fast_tanh(float x) {
    // tanh(x) = 1 - 2/(exp(2x)+1); saturates correctly at +-inf. rel err ~1e-6
    float e = __expf(2.0f * x);
    return 1.0f - __fdividef(2.0f, e + 1.0f);
}

__device__ __forceinline__ void red_add_v4(float* addr, float4 v) {
    asm volatile("red.global.add.v4.f32 [%0], {%1,%2,%3,%4};"
                 :: "l"(addr), "f"(v.x), "f"(v.y), "f"(v.z), "f"(v.w)
                 : "memory");
}

// ---------------- kernel 0: zero accumulators --------------------------------
__global__ void k_zero() {
    int idx = blockIdx.x * blockDim.x + threadIdx.x;
    int stride = gridDim.x * blockDim.x;
    float4 z = make_float4(0.f, 0.f, 0.f, 0.f);
    float4* a = (float4*)g_p1scat;
    for (int i = idx; i < N_ATOMS * 32; i += stride) a[i] = z;
    float4* b = (float4*)g_p3acc;
    for (int i = idx; i < N_ATOMS * 48; i += stride) b[i] = z;
    float4* c = (float4*)g_v;
    for (int i = idx; i < N_ATOMS; i += stride) c[i] = z;
}

// ---------------- kernel V: v = segment_sum(d3 * fc, i) ----------------------
__global__ void k_vscat(const int* __restrict__ ind2,
                        const float* __restrict__ d3,
                        const float* __restrict__ fc_edge) {
    int p = blockIdx.x * blockDim.x + threadIdx.x;
    if (p >= N_PAIRS) return;
    int i = __ldg(&ind2[2 * p]);
    float fc = __ldg(&fc_edge[p]);
    float d0 = __ldg(&d3[3 * p + 0]) * fc;
    float d1 = __ldg(&d3[3 * p + 1]) * fc;
    float d2 = __ldg(&d3[3 * p + 2]) * fc;
    atomicAdd(&g_v[4 * i + 0], d0);
    atomicAdd(&g_v[4 * i + 1], d1);
    atomicAdd(&g_v[4 * i + 2], d2);
}

// ---------------- kernel AB: p1_in MLP + A/B tables --------------------------
// A[a] = p1_in[a] @ pi_W[0:64,:], B[a] = p1_in[a] @ pi_W[64:128,:]
__global__ void k_ab(const float* __restrict__ p1,
                     const float* __restrict__ W1, const float* __restrict__ b1,
                     const float* __restrict__ W2, const float* __restrict__ b2,
                     const float* __restrict__ piW) {
    __shared__ float s_x[32][64];
    __shared__ float s_t[32][64];
    int tid = threadIdx.x;
    int a_base = blockIdx.x * 32;

    // load p1 tile
    for (int e = tid; e < 32 * 64; e += 256) {
        int a = e >> 6, c = e & 63;
        int atom = a_base + a;
        s_x[a][c] = (atom < N_ATOMS) ? __ldg(&p1[atom * 64 + c]) : 0.f;
    }
    __syncthreads();
    // layer 1
    for (int e = tid; e < 32 * 64; e += 256) {
        int a = e >> 6, o = e & 63;
        float acc = __ldg(&b1[o]);
        #pragma unroll 8
        for (int c = 0; c < 64; c++)
            acc = fmaf(s_x[a][c], __ldg(&W1[c * 64 + o]), acc);
        s_t[a][o] = fast_tanh(acc);
    }
    __syncthreads();
    // layer 2 -> p1_in back into s_x
    for (int e = tid; e < 32 * 64; e += 256) {
        int a = e >> 6, o = e & 63;
        float acc = __ldg(&b2[o]);
        #pragma unroll 8
        for (int c = 0; c < 64; c++)
            acc = fmaf(s_t[a][c], __ldg(&W2[c * 64 + o]), acc);
        s_x[a][o] = fast_tanh(acc);
    }
    __syncthreads();

    // A / B tables: 320 output quads (160 A + 160 B), register-blocked 8 atoms
    for (int q = tid; q < 320; q += 256) {
        int isB = (q >= 160);
        int colb = (isB ? (q - 160) : q) * 4;
        const float* Wbase = piW + (isB ? 64 * 640 : 0) + colb;
        float* outBase = isB ? g_B : g_A;
        for (int a0 = 0; a0 < 32; a0 += 8) {
            float4 acc[8];
            #pragma unroll
            for (int a = 0; a < 8; a++) acc[a] = make_float4(0.f, 0.f, 0.f, 0.f);
            for (int c = 0; c < 64; c++) {
                float4 w = __ldg((const float4*)(Wbase + c * 640));
                #pragma unroll
                for (int a = 0; a < 8; a++) {
                    float pv = s_x[a0 + a][c];
                    acc[a].x = fmaf(pv, w.x, acc[a].x);
                    acc[a].y = fmaf(pv, w.y, acc[a].y);
                    acc[a].z = fmaf(pv, w.z, acc[a].z);
                    acc[a].w = fmaf(pv, w.w, acc[a].w);
                }
            }
            #pragma unroll
            for (int a = 0; a < 8; a++) {
                int atom = a_base + a0 + a;
                if (atom < N_ATOMS)
                    *(float4*)(outBase + (size_t)atom * 640 + colb) = acc[a];
            }
        }
    }
}

// ---------------- kernel P: per-pair main body --------------------------------
// warp per pair; 8 pairs per 256-thread block; grid-stride over pair groups
__global__ void k_pairs(const int* __restrict__ ind2,
                        const float* __restrict__ basis,
                        const float* __restrict__ d3,
                        const float* __restrict__ fc_edge,
                        const float* __restrict__ p3,
                        const float* __restrict__ pi_b,
                        const float* __restrict__ ii_W) {
    __shared__ float4 s_ii4[64 * 32];               // ii_W (64x128) as float4
    __shared__ float  s_pib[640];
    __shared__ __align__(16) float s_s[8][64];      // per-warp s vector
    __shared__ float4 s_i1b4[8][16];                // per-warp i1b (64 floats)

    int tid = threadIdx.x;
    int lane = tid & 31;
    int wid = tid >> 5;

    for (int t = tid; t < 64 * 32; t += 256) s_ii4[t] = __ldg(((const float4*)ii_W) + t);
    for (int t = tid; t < 640; t += 256) s_pib[t] = __ldg(&pi_b[t]);
    __syncthreads();

    const int NGROUPS = N_PAIRS / 8;
    for (int g = blockIdx.x; g < NGROUPS; g += gridDim.x) {
        int p = g * 8 + wid;
        int i = __ldg(&ind2[2 * p]);
        int j = __ldg(&ind2[2 * p + 1]);

        // ---- phase A: s[c] = sum_b tanh(A[i]+B[j]+bias) * basis  (2 c per lane)
        float bas[10];
        #pragma unroll
        for (int t = 0; t < 10; t++) bas[t] = __ldg(&basis[(size_t)p * 10 + t]);

        const float4* Ar = (const float4*)(g_A + (size_t)i * 640);
        const float4* Br = (const float4*)(g_B + (size_t)j * 640);
        float sm[20];
        #pragma unroll
        for (int q = 0; q < 5; q++) {
            float4 a4 = __ldg(Ar + lane * 5 + q);
            float4 b4 = __ldg(Br + lane * 5 + q);
            sm[4 * q + 0] = a4.x + b4.x;
            sm[4 * q + 1] = a4.y + b4.y;
            sm[4 * q + 2] = a4.z + b4.z;
            sm[4 * q + 3] = a4.w + b4.w;
        }
        const float* pib = &s_pib[lane * 20];
        float sum0 = 0.f, sum1 = 0.f;
        #pragma unroll
        for (int t = 0; t < 10; t++)
            sum0 = fmaf(fast_tanh(sm[t] + pib[t]), bas[t], sum0);
        #pragma unroll
        for (int t = 0; t < 10; t++)
            sum1 = fmaf(fast_tanh(sm[10 + t] + pib[10 + t]), bas[t], sum1);
        s_s[wid][2 * lane]     = sum0;
        s_s[wid][2 * lane + 1] = sum1;
        __syncwarp();

        // ---- phase B: i_pair = tanh(s @ ii_W); lane owns k = 4*lane..4*lane+3
        float4 acc = make_float4(0.f, 0.f, 0.f, 0.f);
        const float4* sv4 = (const float4*)s_s[wid];
        #pragma unroll
        for (int c4 = 0; c4 < 16; c4++) {
            float4 sv = sv4[c4];
            float4 w0 = s_ii4[(4 * c4 + 0) * 32 + lane];
            acc.x = fmaf(sv.x, w0.x, acc.x); acc.y = fmaf(sv.x, w0.y, acc.y);
            acc.z = fmaf(sv.x, w0.z, acc.z); acc.w = fmaf(sv.x, w0.w, acc.w);
            float4 w1 = s_ii4[(4 * c4 + 1) * 32 + lane];
            acc.x = fmaf(sv.y, w1.x, acc.x); acc.y = fmaf(sv.y, w1.y, acc.y);
            acc.z = fmaf(sv.y, w1.z, acc.z); acc.w = fmaf(sv.y, w1.w, acc.w);
            float4 w2 = s_ii4[(4 * c4 + 2) * 32 + lane];
            acc.x = fmaf(sv.z, w2.x, acc.x); acc.y = fmaf(sv.z, w2.y, acc.y);
            acc.z = fmaf(sv.z, w2.z, acc.z); acc.w = fmaf(sv.z, w2.w, acc.w);
            float4 w3 = s_ii4[(4 * c4 + 3) * 32 + lane];
            acc.x = fmaf(sv.w, w3.x, acc.x); acc.y = fmaf(sv.w, w3.y, acc.y);
            acc.z = fmaf(sv.w, w3.z, acc.z); acc.w = fmaf(sv.w, w3.w, acc.w);
        }
        float4 ip;
        ip.x = fast_tanh(acc.x);
        ip.y = fast_tanh(acc.y);
        ip.z = fast_tanh(acc.z);
        ip.w = fast_tanh(acc.w);

        // p1 segment-sum: vector atomic
        red_add_v4(g_p1scat + (size_t)i * 128 + 4 * lane, ip);

        // stash i1b (= i_pair[64:128]) for whole warp
        if (lane >= 16) s_i1b4[wid][lane - 16] = ip;
        __syncwarp();

        // ---- phase C: pair geometry (redundant per lane; cheap)
        float d0 = __ldg(&d3[3 * p + 0]);
        float d1 = __ldg(&d3[3 * p + 1]);
        float d2 = __ldg(&d3[3 * p + 2]);
        float fc = __ldg(&fc_edge[p]);
        float vx = g_v[4 * i + 0], vy = g_v[4 * i + 1], vz = g_v[4 * i + 2];
        float proj = vx * d0 + vy * d1 + vz * d2;
        float wx = vx - proj * d0, wy = vy - proj * d1, wz = vz - proj * d2;
        float w2 = wx * wx + wy * wy + wz * wz;
        float g_deg = __fdividef(w2, w2 + 1e-4f);      // (10*EPS)^2
        float rs = rsqrtf(w2 + 1e-6f);                  // EPS^2
        float tb = g_deg * fc * fc;
        float sc = rs * g_deg * tb;                     // t3[x]*tb = w[x]*sc
        float term0 = d0 + wx * sc;
        float term1 = d1 + wy * sc;
        float term2 = d2 + wz * sc;

        // ---- phase D: p3 segment-sum: ix = i1b[c]*(p3[j]+d3+t3*tb)
        const float4* p3j = (const float4*)(p3 + (size_t)j * 192);
        float* accBase = g_p3acc + (size_t)i * 192;
        #pragma unroll
        for (int it = 0; it < 2; it++) {
            int t = lane + 32 * it;
            if (t < 48) {
                int x = t >> 4;
                int m = t & 15;
                float4 gg = s_i1b4[wid][m];
                float4 pj = __ldg(&p3j[x * 16 + m]);
                float tm = (x == 0) ? term0 : ((x == 1) ? term1 : term2);
                float4 val;
                val.x = gg.x * (pj.x + tm);
                val.y = gg.y * (pj.y + tm);
                val.z = gg.z * (pj.z + tm);
                val.w = gg.w * (pj.w + tm);
                red_add_v4(accBase + x * 64 + 4 * m, val);
            }
        }
    }
}

// ---------------- kernel F: atom finalize ------------------------------------
__global__ void k_final(const float* __restrict__ postW1,
                        const float* __restrict__ postW2,
                        const float* __restrict__ eqW,
                        const float* __restrict__ q1W1,
                        const float* __restrict__ q1b1,
                        const float* __restrict__ q1W2,
                        const float* __restrict__ q1b2,
                        float* __restrict__ out) {
    __shared__ float s_scat[8][128];
    __shared__ float s_acc[8][192];
    __shared__ float s_t1[8][64];
    __shared__ float s_cat[8][128];
    __shared__ float s_h2a[8][64];

    int tid = threadIdx.x;
    int lane = tid & 31;
    int wid = tid >> 5;
    int a = blockIdx.x * 8 + wid;   // grid=1250 -> exact

    for (int t = lane; t < 128; t += 32) s_scat[wid][t] = g_p1scat[(size_t)a * 128 + t];
    for (int t = lane; t < 192; t += 32) s_acc[wid][t] = g_p3acc[(size_t)a * 192 + t];
    __syncwarp();

    // t1 = tanh(scat @ postW1)
    #pragma unroll
    for (int oi = 0; oi < 2; oi++) {
        int o = lane + 32 * oi;
        float acc = 0.f;
        #pragma unroll 8
        for (int c = 0; c < 128; c++)
            acc = fmaf(s_scat[wid][c], __ldg(&postW1[c * 64 + o]), acc);
        s_t1[wid][o] = fast_tanh(acc);
    }
    __syncwarp();

    // p1_new = tanh(t1 @ postW2)
    #pragma unroll
    for (int oi = 0; oi < 2; oi++) {
        int o = lane + 32 * oi;
        float acc = 0.f;
        #pragma unroll 8
        for (int c = 0; c < 64; c++)
            acc = fmaf(s_t1[wid][c], __ldg(&postW2[c * 64 + o]), acc);
        s_cat[wid][o] = fast_tanh(acc);
    }

    // p3_new = p3acc @ eqW  (per lane: c=lane, lane+32; x=0..2)
    float p3n[3][2];
    #pragma unroll
    for (int x = 0; x < 3; x++) {
        float a0 = 0.f, a1 = 0.f;
        #pragma unroll 8
        for (int cin = 0; cin < 64; cin++) {
            float av = s_acc[wid][x * 64 + cin];
            a0 = fmaf(av, __ldg(&eqW[cin * 64 + lane]), a0);
            a1 = fmaf(av, __ldg(&eqW[cin * 64 + lane + 32]), a1);
        }
        p3n[x][0] = a0;
        p3n[x][1] = a1;
    }
    // dotted
    #pragma unroll
    for (int ci = 0; ci < 2; ci++) {
        float d = p3n[0][ci] * p3n[0][ci] + p3n[1][ci] * p3n[1][ci] +
                  p3n[2][ci] * p3n[2][ci];
        s_cat[wid][64 + lane + 32 * ci] = d;
    }
    __syncwarp();

    // h2a = tanh(cat @ q1W1 + b1)
    #pragma unroll
    for (int oi = 0; oi < 2; oi++) {
        int o = lane + 32 * oi;
        float acc = __ldg(&q1b1[o]);
        #pragma unroll 8
        for (int c = 0; c < 128; c++)
            acc = fmaf(s_cat[wid][c], __ldg(&q1W1[c * 64 + o]), acc);
        s_h2a[wid][o] = fast_tanh(acc);
    }
    __syncwarp();

    // h2 = tanh(h2a @ q1W2 + b2); g1 = h2[:64], g3 = h2[64:]
    float h2[4];
    #pragma unroll
    for (int ki = 0; ki < 4; ki++) {
        int k = lane + 32 * ki;
        float acc = __ldg(&q1b2[k]);
        #pragma unroll 8
        for (int o = 0; o < 64; o++)
            acc = fmaf(s_h2a[wid][o], __ldg(&q1W2[o * 128 + k]), acc);
        h2[ki] = fast_tanh(acc);
    }

    // p1_out
    out[(size_t)a * 64 + lane] = h2[0];
    out[(size_t)a * 64 + lane + 32] = h2[1];
    // p3_out = p3_new * g3
    float* o3 = out + (size_t)N_ATOMS * 64 + (size_t)a * 192;
    #pragma unroll
    for (int x = 0; x < 3; x++) {
        o3[x * 64 + lane] = p3n[x][0] * h2[2];
        o3[x * 64 + lane + 32] = p3n[x][1] * h2[3];
    }
}

// ---------------- launch ------------------------------------------------------
extern "C" void kernel_launch(void* const* d_in, const int* in_sizes, int n_in,
                              void* d_out, int out_size) {
    const int*   ind2    = (const int*)d_in[0];
    const float* p1      = (const float*)d_in[1];
    const float* p3      = (const float*)d_in[2];
    const float* basis   = (const float*)d_in[3];
    const float* d3      = (const float*)d_in[4];
    const float* fc_edge = (const float*)d_in[5];
    const float* ppreW1  = (const float*)d_in[6];
    const float* ppreb1  = (const float*)d_in[7];
    const float* ppreW2  = (const float*)d_in[8];
    const float* ppreb2  = (const float*)d_in[9];
    const float* piW     = (const float*)d_in[10];
    const float* pib     = (const float*)d_in[11];
    const float* iiW     = (const float*)d_in[12];
    const float* postW1  = (const float*)d_in[13];
    const float* postW2  = (const float*)d_in[14];
    const float* eqW     = (const float*)d_in[15];
    const float* q1W1    = (const float*)d_in[16];
    const float* q1b1    = (const float*)d_in[17];
    const float* q1W2    = (const float*)d_in[18];
    const float* q1b2    = (const float*)d_in[19];
    float* out = (float*)d_out;

    k_zero<<<512, 256>>>();
    k_vscat<<<(N_PAIRS + 255) / 256, 256>>>(ind2, d3, fc_edge);
    k_ab<<<(N_ATOMS + 31) / 32, 256>>>(p1, ppreW1, ppreb1, ppreW2, ppreb2, piW);
    k_pairs<<<4440, 256>>>(ind2, basis, d3, fc_edge, p3, pib, iiW);
    k_final<<<N_ATOMS / 8, 256>>>(postW1, postW2, eqW, q1W1, q1b1, q1W2, q1b2, out);
}

// round 6
// speedup vs baseline: 1.6831x; 1.6831x over previous
#include <cuda_runtime.h>
#include <math.h>
#include <stdint.h>

#define N_ATOMS 10000
#define N_PAIRS 320000
#define PB 4   // pairs per warp batch in k_pairs

// ---------------- scratch (static device globals; no runtime alloc) ----------
// A/B layout: [atom][b2*128 + c*2 + (b&1)]  (b2 = b/2)  -> coalesced gathers
__device__ __align__(16) float g_A[N_ATOMS * 640];
__device__ __align__(16) float g_B[N_ATOMS * 640];
__device__ __align__(16) float g_v[N_ATOMS * 4];
__device__ __align__(16) float g_p1scat[N_ATOMS * 128];
__device__ __align__(16) float g_p3acc[N_ATOMS * 192];

// ---------------- helpers ----------------------------------------------------
__device__ __forceinline__ float fast_tanh(float x) {
    // accurate: rel err ~1e-6
    float e = __expf(2.0f * x);
    return 1.0f - __fdividef(2.0f, e + 1.0f);
}
__device__ __forceinline__ float tanh_hw(float x) {
    // MUFU.TANH, abs err ~1.5e-4 (used only in phase-A inner loop)
    float y;
    asm("tanh.approx.f32 %0, %1;" : "=f"(y) : "f"(x));
    return y;
}
__device__ __forceinline__ void red_add_v4(float* addr, float4 v) {
    asm volatile("red.global.add.v4.f32 [%0], {%1,%2,%3,%4};"
                 :: "l"(addr), "f"(v.x), "f"(v.y), "f"(v.z), "f"(v.w)
                 : "memory");
}

// ---------------- kernel 0: zero accumulators --------------------------------
__global__ void k_zero() {
    int idx = blockIdx.x * blockDim.x + threadIdx.x;
    int stride = gridDim.x * blockDim.x;
    float4 z = make_float4(0.f, 0.f, 0.f, 0.f);
    float4* a = (float4*)g_p1scat;
    for (int i = idx; i < N_ATOMS * 32; i += stride) a[i] = z;
    float4* b = (float4*)g_p3acc;
    for (int i = idx; i < N_ATOMS * 48; i += stride) b[i] = z;
    float4* c = (float4*)g_v;
    for (int i = idx; i < N_ATOMS; i += stride) c[i] = z;
}

// ---------------- kernel V: v = segment_sum(d3 * fc, i) ----------------------
__global__ void k_vscat(const int* __restrict__ ind2,
                        const float* __restrict__ d3,
                        const float* __restrict__ fc_edge) {
    int p = blockIdx.x * blockDim.x + threadIdx.x;
    if (p >= N_PAIRS) return;
    int2 ij = __ldg((const int2*)ind2 + p);
    float fc = __ldg(&fc_edge[p]);
    float4 val;
    val.x = __ldg(&d3[3 * p + 0]) * fc;
    val.y = __ldg(&d3[3 * p + 1]) * fc;
    val.z = __ldg(&d3[3 * p + 2]) * fc;
    val.w = 0.f;
    red_add_v4(&g_v[4 * ij.x], val);
}

// ---------------- kernel AB: p1_in MLP + A/B tables (b-major, bias folded) ---
__global__ void k_ab(const float* __restrict__ p1,
                     const float* __restrict__ W1, const float* __restrict__ b1,
                     const float* __restrict__ W2, const float* __restrict__ b2,
                     const float* __restrict__ piW,
                     const float* __restrict__ pib) {
    __shared__ float s_x[32][64];
    __shared__ float s_t[32][64];
    int tid = threadIdx.x;
    int a_base = blockIdx.x * 32;

    for (int e = tid; e < 32 * 64; e += 256) {
        int a = e >> 6, c = e & 63;
        int atom = a_base + a;
        s_x[a][c] = (atom < N_ATOMS) ? __ldg(&p1[atom * 64 + c]) : 0.f;
    }
    __syncthreads();
    for (int e = tid; e < 32 * 64; e += 256) {
        int a = e >> 6, o = e & 63;
        float acc = __ldg(&b1[o]);
        #pragma unroll 8
        for (int c = 0; c < 64; c++)
            acc = fmaf(s_x[a][c], __ldg(&W1[c * 64 + o]), acc);
        s_t[a][o] = fast_tanh(acc);
    }
    __syncthreads();
    for (int e = tid; e < 32 * 64; e += 256) {
        int a = e >> 6, o = e & 63;
        float acc = __ldg(&b2[o]);
        #pragma unroll 8
        for (int c = 0; c < 64; c++)
            acc = fmaf(s_t[a][c], __ldg(&W2[c * 64 + o]), acc);
        s_x[a][o] = fast_tanh(acc);
    }
    __syncthreads();

    // A/B tables in new layout. quad q: table, r = q%160, c0=(r/5)*2, b2=r%5
    // out[atom][b2*128 + c0*2 + e]: e0=(c0,2b2) e1=(c0,2b2+1) e2=(c0+1,2b2) e3=(c0+1,2b2+1)
    for (int q = tid; q < 320; q += 256) {
        int isB = (q >= 160);
        int r = isB ? (q - 160) : q;
        int c0 = (r / 5) * 2;
        int b2i = r - (r / 5) * 5;
        const float* Wb = piW + (isB ? 64 * 640 : 0) + c0 * 10 + 2 * b2i;
        float* outB = (isB ? g_B : g_A) + b2i * 128 + c0 * 2;
        float2 bi0 = make_float2(0.f, 0.f), bi1 = make_float2(0.f, 0.f);
        if (!isB) {
            bi0 = __ldg((const float2*)(pib + c0 * 10 + 2 * b2i));
            bi1 = __ldg((const float2*)(pib + c0 * 10 + 2 * b2i + 10));
        }
        for (int a0 = 0; a0 < 32; a0 += 8) {
            float4 acc[8];
            #pragma unroll
            for (int a = 0; a < 8; a++) acc[a] = make_float4(0.f, 0.f, 0.f, 0.f);
            for (int ci = 0; ci < 64; ci++) {
                float2 wa = __ldg((const float2*)(Wb + ci * 640));
                float2 wb = __ldg((const float2*)(Wb + ci * 640 + 10));
                #pragma unroll
                for (int a = 0; a < 8; a++) {
                    float pv = s_x[a0 + a][ci];
                    acc[a].x = fmaf(pv, wa.x, acc[a].x);
                    acc[a].y = fmaf(pv, wa.y, acc[a].y);
                    acc[a].z = fmaf(pv, wb.x, acc[a].z);
                    acc[a].w = fmaf(pv, wb.y, acc[a].w);
                }
            }
            #pragma unroll
            for (int a = 0; a < 8; a++) {
                int atom = a_base + a0 + a;
                if (atom < N_ATOMS) {
                    acc[a].x += bi0.x; acc[a].y += bi0.y;
                    acc[a].z += bi1.x; acc[a].w += bi1.y;
                    *(float4*)(outB + (size_t)atom * 640) = acc[a];
                }
            }
        }
    }
}

// ---------------- kernel P: per-pair main body --------------------------------
// warp handles PB=4 pairs; 8 warps/block; grid-stride over groups of 32 pairs
__global__ void __launch_bounds__(256) k_pairs(
        const int* __restrict__ ind2,
        const float* __restrict__ basis,
        const float* __restrict__ d3,
        const float* __restrict__ fc_edge,
        const float* __restrict__ p3,
        const float* __restrict__ ii_W) {
    __shared__ float4 s_ii4[64 * 32];                      // 32 KB
    __shared__ __align__(16) float s_s[8][PB][64];         // 8 KB
    __shared__ float4 s_i1b[8][PB][16];                    // 8 KB

    int tid = threadIdx.x;
    int lane = tid & 31;
    int wid = tid >> 5;

    for (int t = tid; t < 64 * 32; t += 256)
        s_ii4[t] = __ldg(((const float4*)ii_W) + t);
    __syncthreads();

    const int NG = N_PAIRS / (8 * PB);
    for (int g = blockIdx.x; g < NG; g += gridDim.x) {
        int pbase = (g * 8 + wid) * PB;
        int ii_[PB], jj_[PB];

        // ---- phase A per pair: s = sum_b tanh(A[i]+B[j]) * basis
        #pragma unroll
        for (int pp = 0; pp < PB; pp++) {
            int p = pbase + pp;
            int2 ij = __ldg((const int2*)ind2 + p);
            ii_[pp] = ij.x; jj_[pp] = ij.y;
            const float2* basf = (const float2*)(basis + (size_t)p * 10);
            const float4* Ar = (const float4*)(g_A + (size_t)ij.x * 640);
            const float4* Br = (const float4*)(g_B + (size_t)ij.y * 640);
            float sum0 = 0.f, sum1 = 0.f;
            #pragma unroll
            for (int b2i = 0; b2i < 5; b2i++) {
                float4 a4 = __ldg(Ar + b2i * 32 + lane);
                float4 b4 = __ldg(Br + b2i * 32 + lane);
                float2 bb = __ldg(basf + b2i);
                float t0 = tanh_hw(a4.x + b4.x);
                float t1 = tanh_hw(a4.y + b4.y);
                float t2 = tanh_hw(a4.z + b4.z);
                float t3 = tanh_hw(a4.w + b4.w);
                sum0 = fmaf(t0, bb.x, sum0);
                sum0 = fmaf(t1, bb.y, sum0);
                sum1 = fmaf(t2, bb.x, sum1);
                sum1 = fmaf(t3, bb.y, sum1);
            }
            *(float2*)&s_s[wid][pp][2 * lane] = make_float2(sum0, sum1);
        }
        __syncwarp();

        // ---- phase B: i_pair = tanh(s @ ii_W), 4 pairs share each weight load
        float4 acc[PB];
        #pragma unroll
        for (int pp = 0; pp < PB; pp++) acc[pp] = make_float4(0.f, 0.f, 0.f, 0.f);
        #pragma unroll
        for (int c4 = 0; c4 < 16; c4++) {
            float4 w0 = s_ii4[(4 * c4 + 0) * 32 + lane];
            float4 w1 = s_ii4[(4 * c4 + 1) * 32 + lane];
            float4 w2 = s_ii4[(4 * c4 + 2) * 32 + lane];
            float4 w3 = s_ii4[(4 * c4 + 3) * 32 + lane];
            #pragma unroll
            for (int pp = 0; pp < PB; pp++) {
                float4 sv = ((const float4*)s_s[wid][pp])[c4];
                acc[pp].x = fmaf(sv.x, w0.x, acc[pp].x); acc[pp].y = fmaf(sv.x, w0.y, acc[pp].y);
                acc[pp].z = fmaf(sv.x, w0.z, acc[pp].z); acc[pp].w = fmaf(sv.x, w0.w, acc[pp].w);
                acc[pp].x = fmaf(sv.y, w1.x, acc[pp].x); acc[pp].y = fmaf(sv.y, w1.y, acc[pp].y);
                acc[pp].z = fmaf(sv.y, w1.z, acc[pp].z); acc[pp].w = fmaf(sv.y, w1.w, acc[pp].w);
                acc[pp].x = fmaf(sv.z, w2.x, acc[pp].x); acc[pp].y = fmaf(sv.z, w2.y, acc[pp].y);
                acc[pp].z = fmaf(sv.z, w2.z, acc[pp].z); acc[pp].w = fmaf(sv.z, w2.w, acc[pp].w);
                acc[pp].x = fmaf(sv.w, w3.x, acc[pp].x); acc[pp].y = fmaf(sv.w, w3.y, acc[pp].y);
                acc[pp].z = fmaf(sv.w, w3.z, acc[pp].z); acc[pp].w = fmaf(sv.w, w3.w, acc[pp].w);
            }
        }
        #pragma unroll
        for (int pp = 0; pp < PB; pp++) {
            float4 ip;
            ip.x = fast_tanh(acc[pp].x);
            ip.y = fast_tanh(acc[pp].y);
            ip.z = fast_tanh(acc[pp].z);
            ip.w = fast_tanh(acc[pp].w);
            red_add_v4(g_p1scat + (size_t)ii_[pp] * 128 + 4 * lane, ip);
            if (lane >= 16) s_i1b[wid][pp][lane - 16] = ip;
        }
        __syncwarp();

        // ---- phases C+D per pair
        #pragma unroll
        for (int pp = 0; pp < PB; pp++) {
            int p = pbase + pp;
            int i = ii_[pp], j = jj_[pp];
            float d0 = __ldg(&d3[3 * p + 0]);
            float d1 = __ldg(&d3[3 * p + 1]);
            float d2 = __ldg(&d3[3 * p + 2]);
            float fc = __ldg(&fc_edge[p]);
            float4 v4 = __ldg((const float4*)g_v + i);
            float proj = v4.x * d0 + v4.y * d1 + v4.z * d2;
            float wx = v4.x - proj * d0, wy = v4.y - proj * d1, wz = v4.z - proj * d2;
            float w2 = wx * wx + wy * wy + wz * wz;
            float g_deg = __fdividef(w2, w2 + 1e-4f);
            float rs = rsqrtf(w2 + 1e-6f);
            float tb = g_deg * fc * fc;
            float sc = rs * g_deg * tb;
            float term0 = d0 + wx * sc;
            float term1 = d1 + wy * sc;
            float term2 = d2 + wz * sc;

            const float4* p3j = (const float4*)(p3 + (size_t)j * 192);
            float* accBase = g_p3acc + (size_t)i * 192;
            #pragma unroll
            for (int it = 0; it < 2; it++) {
                int t = lane + 32 * it;
                if (t < 48) {
                    int x = t >> 4;
                    int m = t & 15;
                    float4 gg = s_i1b[wid][pp][m];
                    float4 pj = __ldg(&p3j[x * 16 + m]);
                    float tm = (x == 0) ? term0 : ((x == 1) ? term1 : term2);
                    float4 val;
                    val.x = gg.x * (pj.x + tm);
                    val.y = gg.y * (pj.y + tm);
                    val.z = gg.z * (pj.z + tm);
                    val.w = gg.w * (pj.w + tm);
                    red_add_v4(accBase + x * 64 + 4 * m, val);
                }
            }
        }
    }
}

// ---------------- kernel F: atom finalize (32 atoms/block, 8-atom reg block) --
__global__ void __launch_bounds__(256) k_final(
        const float* __restrict__ postW1,
        const float* __restrict__ postW2,
        const float* __restrict__ eqW,
        const float* __restrict__ q1W1,
        const float* __restrict__ q1b1,
        const float* __restrict__ q1W2,
        const float* __restrict__ q1b2,
        float* __restrict__ out) {
    __shared__ float s_cat[32][128];   // scat (phase1) then [p1_new | dotted]
    __shared__ float s_acc[32][192];   // p3acc tile
    __shared__ float s_b[32][64];      // t1 then h2a

    int tid = threadIdx.x;
    int o = tid & 63;
    int g = tid >> 6;          // 0..3, each handles 8 atoms
    int a_base = blockIdx.x * 32;
    float4 z4 = make_float4(0.f, 0.f, 0.f, 0.f);

    for (int e = tid; e < 32 * 32; e += 256) {
        int a = e >> 5, c4 = e & 31;
        int atom = a_base + a;
        ((float4*)s_cat[a])[c4] = (atom < N_ATOMS)
            ? __ldg((const float4*)(g_p1scat + (size_t)atom * 128) + c4) : z4;
    }
    for (int e = tid; e < 32 * 48; e += 256) {
        int a = e / 48, c4 = e % 48;
        int atom = a_base + a;
        ((float4*)s_acc[a])[c4] = (atom < N_ATOMS)
            ? __ldg((const float4*)(g_p3acc + (size_t)atom * 192) + c4) : z4;
    }
    __syncthreads();

    // phase1: t1 = tanh(scat @ postW1) -> s_b
    {
        float accv[8];
        #pragma unroll
        for (int u = 0; u < 8; u++) accv[u] = 0.f;
        for (int c = 0; c < 128; c++) {
            float w = __ldg(&postW1[c * 64 + o]);
            #pragma unroll
            for (int u = 0; u < 8; u++)
                accv[u] = fmaf(s_cat[8 * g + u][c], w, accv[u]);
        }
        __syncthreads();   // scat reads done before overwrite below
        #pragma unroll
        for (int u = 0; u < 8; u++) s_b[8 * g + u][o] = fast_tanh(accv[u]);
    }
    __syncthreads();

    // phase2: p1_new = tanh(t1 @ postW2) -> s_cat[:, 0:64]
    {
        float accv[8];
        #pragma unroll
        for (int u = 0; u < 8; u++) accv[u] = 0.f;
        for (int c = 0; c < 64; c++) {
            float w = __ldg(&postW2[c * 64 + o]);
            #pragma unroll
            for (int u = 0; u < 8; u++)
                accv[u] = fmaf(s_b[8 * g + u][c], w, accv[u]);
        }
        #pragma unroll
        for (int u = 0; u < 8; u++) s_cat[8 * g + u][o] = fast_tanh(accv[u]);
    }

    // phase3: p3n (regs) + dotted -> s_cat[:, 64:128]
    float p3n[3][8];
    #pragma unroll
    for (int x = 0; x < 3; x++) {
        float accv[8];
        #pragma unroll
        for (int u = 0; u < 8; u++) accv[u] = 0.f;
        for (int c = 0; c < 64; c++) {
            float w = __ldg(&eqW[c * 64 + o]);
            #pragma unroll
            for (int u = 0; u < 8; u++)
                accv[u] = fmaf(s_acc[8 * g + u][x * 64 + c], w, accv[u]);
        }
        #pragma unroll
        for (int u = 0; u < 8; u++) p3n[x][u] = accv[u];
    }
    #pragma unroll
    for (int u = 0; u < 8; u++)
        s_cat[8 * g + u][64 + o] = p3n[0][u] * p3n[0][u] +
                                   p3n[1][u] * p3n[1][u] +
                                   p3n[2][u] * p3n[2][u];
    __syncthreads();

    // phase4: h2a = tanh(cat @ q1W1 + b1) -> s_b
    {
        float accv[8];
        float bias = __ldg(&q1b1[o]);
        #pragma unroll
        for (int u = 0; u < 8; u++) accv[u] = bias;
        for (int c = 0; c < 128; c++) {
            float w = __ldg(&q1W1[c * 64 + o]);
            #pragma unroll
            for (int u = 0; u < 8; u++)
                accv[u] = fmaf(s_cat[8 * g + u][c], w, accv[u]);
        }
        __syncthreads();   // s_b(t1) reads done in phase2
        #pragma unroll
        for (int u = 0; u < 8; u++) s_b[8 * g + u][o] = fast_tanh(accv[u]);
    }
    __syncthreads();

    // phase5: h2 = tanh(h2a @ q1W2 + b2); write outputs
    {
        float h0[8], h1[8];
        float bias0 = __ldg(&q1b2[o]);
        float bias1 = __ldg(&q1b2[o + 64]);
        #pragma unroll
        for (int u = 0; u < 8; u++) { h0[u] = bias0; h1[u] = bias1; }
        for (int c = 0; c < 64; c++) {
            float w0 = __ldg(&q1W2[c * 128 + o]);
            float w1 = __ldg(&q1W2[c * 128 + o + 64]);
            #pragma unroll
            for (int u = 0; u < 8; u++) {
                float v = s_b[8 * g + u][c];
                h0[u] = fmaf(v, w0, h0[u]);
                h1[u] = fmaf(v, w1, h1[u]);
            }
        }
        #pragma unroll
        for (int u = 0; u < 8; u++) {
            int atom = a_base + 8 * g + u;
            if (atom < N_ATOMS) {
                float g1 = fast_tanh(h0[u]);
                float g3 = fast_tanh(h1[u]);
                out[(size_t)atom * 64 + o] = g1;
                float* o3 = out + (size_t)N_ATOMS * 64 + (size_t)atom * 192;
                #pragma unroll
                for (int x = 0; x < 3; x++)
                    o3[x * 64 + o] = p3n[x][u] * g3;
            }
        }
    }
}

// ---------------- launch ------------------------------------------------------
extern "C" void kernel_launch(void* const* d_in, const int* in_sizes, int n_in,
                              void* d_out, int out_size) {
    const int*   ind2    = (const int*)d_in[0];
    const float* p1      = (const float*)d_in[1];
    const float* p3      = (const float*)d_in[2];
    const float* basis   = (const float*)d_in[3];
    const float* d3      = (const float*)d_in[4];
    const float* fc_edge = (const float*)d_in[5];
    const float* ppreW1  = (const float*)d_in[6];
    const float* ppreb1  = (const float*)d_in[7];
    const float* ppreW2  = (const float*)d_in[8];
    const float* ppreb2  = (const float*)d_in[9];
    const float* piW     = (const float*)d_in[10];
    const float* pib     = (const float*)d_in[11];
    const float* iiW     = (const float*)d_in[12];
    const float* postW1  = (const float*)d_in[13];
    const float* postW2  = (const float*)d_in[14];
    const float* eqW     = (const float*)d_in[15];
    const float* q1W1    = (const float*)d_in[16];
    const float* q1b1    = (const float*)d_in[17];
    const float* q1W2    = (const float*)d_in[18];
    const float* q1b2    = (const float*)d_in[19];
    float* out = (float*)d_out;

    k_zero<<<512, 256>>>();
    k_vscat<<<(N_PAIRS + 255) / 256, 256>>>(ind2, d3, fc_edge);
    k_ab<<<(N_ATOMS + 31) / 32, 256>>>(p1, ppreW1, ppreb1, ppreW2, ppreb2, piW, pib);
    k_pairs<<<592, 256>>>(ind2, basis, d3, fc_edge, p3, iiW);
    k_final<<<(N_ATOMS + 31) / 32, 256>>>(postW1, postW2, eqW, q1W1, q1b1, q1W2, q1b2, out);
}

// round 11
// speedup vs baseline: 1.9618x; 1.1656x over previous
#include <cuda_runtime.h>
#include <math.h>
#include <stdint.h>

#define N_ATOMS 10000
#define N_PAIRS 320000
#define PB 4   // pairs per warp batch in k_pairs

// ---------------- scratch (static device globals; no runtime alloc) ----------
// A/B layout: [atom][b2*128 + c*2 + (b&1)]  (b2 = b/2)  -> coalesced gathers
__device__ __align__(16) float g_A[N_ATOMS * 640];
__device__ __align__(16) float g_B[N_ATOMS * 640];
__device__ __align__(16) float g_p1in[N_ATOMS * 64];
__device__ __align__(16) float g_v[N_ATOMS * 4];
__device__ __align__(16) float g_p1scat[N_ATOMS * 128];
__device__ __align__(16) float g_p3acc[N_ATOMS * 192];

// ---------------- helpers ----------------------------------------------------
__device__ __forceinline__ float fast_tanh(float x) {
    // accurate: rel err ~1e-6
    float e = __expf(2.0f * x);
    return 1.0f - __fdividef(2.0f, e + 1.0f);
}
__device__ __forceinline__ float tanh_hw(float x) {
    // MUFU.TANH, abs err ~1.5e-4 (phase-A inner loop only)
    float y;
    asm("tanh.approx.f32 %0, %1;" : "=f"(y) : "f"(x));
    return y;
}
__device__ __forceinline__ void red_add_v4(float* addr, float4 v) {
    asm volatile("red.global.add.v4.f32 [%0], {%1,%2,%3,%4};"
                 :: "l"(addr), "f"(v.x), "f"(v.y), "f"(v.z), "f"(v.w)
                 : "memory");
}

// ---------------- kernel 0: zero accumulators --------------------------------
__global__ void k_zero() {
    int idx = blockIdx.x * blockDim.x + threadIdx.x;
    int stride = gridDim.x * blockDim.x;
    float4 z = make_float4(0.f, 0.f, 0.f, 0.f);
    float4* a = (float4*)g_p1scat;
    for (int i = idx; i < N_ATOMS * 32; i += stride) a[i] = z;
    float4* b = (float4*)g_p3acc;
    for (int i = idx; i < N_ATOMS * 48; i += stride) b[i] = z;
    float4* c = (float4*)g_v;
    for (int i = idx; i < N_ATOMS; i += stride) c[i] = z;
}

// ---------------- kernel V: v = segment_sum(d3 * fc, i) ----------------------
__global__ void k_vscat(const int* __restrict__ ind2,
                        const float* __restrict__ d3,
                        const float* __restrict__ fc_edge) {
    int p = blockIdx.x * blockDim.x + threadIdx.x;
    if (p >= N_PAIRS) return;
    int2 ij = __ldg((const int2*)ind2 + p);
    float fc = __ldg(&fc_edge[p]);
    float4 val;
    val.x = __ldg(&d3[3 * p + 0]) * fc;
    val.y = __ldg(&d3[3 * p + 1]) * fc;
    val.z = __ldg(&d3[3 * p + 2]) * fc;
    val.w = 0.f;
    red_add_v4(&g_v[4 * ij.x], val);
}

// ---------------- kernel AB1: p1_in = tanh(tanh(p1@W1+b1)@W2+b2) -> global ---
__global__ void k_ab1(const float* __restrict__ p1,
                      const float* __restrict__ W1, const float* __restrict__ b1,
                      const float* __restrict__ W2, const float* __restrict__ b2) {
    __shared__ float s_x[32][64];
    __shared__ float s_t[32][64];
    int tid = threadIdx.x;
    int a_base = blockIdx.x * 32;

    for (int e = tid; e < 32 * 64; e += 256) {
        int a = e >> 6, c = e & 63;
        int atom = a_base + a;
        s_x[a][c] = (atom < N_ATOMS) ? __ldg(&p1[atom * 64 + c]) : 0.f;
    }
    __syncthreads();
    for (int e = tid; e < 32 * 64; e += 256) {
        int a = e >> 6, o = e & 63;
        float acc = __ldg(&b1[o]);
        #pragma unroll 8
        for (int c = 0; c < 64; c++)
            acc = fmaf(s_x[a][c], __ldg(&W1[c * 64 + o]), acc);
        s_t[a][o] = fast_tanh(acc);
    }
    __syncthreads();
    for (int e = tid; e < 32 * 64; e += 256) {
        int a = e >> 6, o = e & 63;
        int atom = a_base + a;
        if (atom >= N_ATOMS) continue;
        float acc = __ldg(&b2[o]);
        #pragma unroll 8
        for (int c = 0; c < 64; c++)
            acc = fmaf(s_t[a][c], __ldg(&W2[c * 64 + o]), acc);
        g_p1in[atom * 64 + o] = fast_tanh(acc);
    }
}

// ---------------- kernel AB2: tiled GEMM -> A/B tables (b-major, bias folded) -
// Output n-space [0,1280): table = n/640, r=n%640, b2i=r/128, c=(r%128)/2, e=r&1
// src weight = piW[(k+64*table)*640 + c*10 + 2*b2i + e]
// BM=128 atoms, BN=64 cols, K=64. grid = (79 atom tiles) x (20 col tiles)
__global__ void __launch_bounds__(256) k_ab2(const float* __restrict__ piW,
                                             const float* __restrict__ pib) {
    __shared__ __align__(16) float s_a[64 * 132];   // [k][atom], pad 132
    __shared__ __align__(16) float s_w[64 * 64];    // [k][n_local] permuted

    int tid = threadIdx.x;
    int tx = tid & 15;          // quad col 0..15
    int ty = tid >> 4;          // atom group 0..15 (8 atoms each)
    int at = blockIdx.x;        // atom tile
    int ct = blockIdx.y;        // col tile 0..19 (0-9 = A, 10-19 = B)
    int a_base = at * 128;
    int table = ct / 10;
    int nb_base = (ct - table * 10) * 64;   // n within table

    // stage A-tile transposed: s_a[k][a]
    for (int l = tid; l < 128 * 16; l += 256) {     // 128 atoms x 16 float4
        int a = l >> 4, kq = l & 15;
        int atom = a_base + a;
        float4 v = (atom < N_ATOMS)
            ? __ldg((const float4*)(g_p1in + (size_t)atom * 64) + kq)
            : make_float4(0.f, 0.f, 0.f, 0.f);
        s_a[(4 * kq + 0) * 132 + a] = v.x;
        s_a[(4 * kq + 1) * 132 + a] = v.y;
        s_a[(4 * kq + 2) * 132 + a] = v.z;
        s_a[(4 * kq + 3) * 132 + a] = v.w;
    }
    // stage W-tile permuted
    for (int l = tid; l < 64 * 64; l += 256) {
        int k = l >> 6, nl = l & 63;
        int nb = nb_base + nl;
        int b2i = nb >> 7;
        int rr = nb & 127;
        int c = rr >> 1;
        int e = rr & 1;
        s_w[l] = __ldg(&piW[(size_t)(k + 64 * table) * 640 + c * 10 + 2 * b2i + e]);
    }
    __syncthreads();

    float4 acc[8];
    #pragma unroll
    for (int u = 0; u < 8; u++) acc[u] = make_float4(0.f, 0.f, 0.f, 0.f);

    const float4* sa4 = (const float4*)s_a;
    const float4* sw4 = (const float4*)s_w;
    #pragma unroll 4
    for (int k = 0; k < 64; k++) {
        float4 w = sw4[k * 16 + tx];
        float4 a0 = sa4[k * 33 + 2 * ty];
        float4 a1 = sa4[k * 33 + 2 * ty + 1];
        float av[8] = {a0.x, a0.y, a0.z, a0.w, a1.x, a1.y, a1.z, a1.w};
        #pragma unroll
        for (int u = 0; u < 8; u++) {
            acc[u].x = fmaf(av[u], w.x, acc[u].x);
            acc[u].y = fmaf(av[u], w.y, acc[u].y);
            acc[u].z = fmaf(av[u], w.z, acc[u].z);
            acc[u].w = fmaf(av[u], w.w, acc[u].w);
        }
    }

    // bias (A table only): pib in same permuted n-space
    float4 bias = make_float4(0.f, 0.f, 0.f, 0.f);
    if (table == 0) {
        int nb = nb_base + 4 * tx;
        int b2i = nb >> 7;
        int rr = nb & 127;
        int c = rr >> 1;
        // quad spans e=0,1 at c and c+1 (nb multiple of 4 -> e starts 0)
        bias.x = __ldg(&pib[c * 10 + 2 * b2i]);
        bias.y = __ldg(&pib[c * 10 + 2 * b2i + 1]);
        bias.z = __ldg(&pib[(c + 1) * 10 + 2 * b2i]);
        bias.w = __ldg(&pib[(c + 1) * 10 + 2 * b2i + 1]);
    }

    float* outT = table ? g_B : g_A;
    #pragma unroll
    for (int u = 0; u < 8; u++) {
        int atom = a_base + 8 * ty + u;
        if (atom < N_ATOMS) {
            float4 r;
            r.x = acc[u].x + bias.x;
            r.y = acc[u].y + bias.y;
            r.z = acc[u].z + bias.z;
            r.w = acc[u].w + bias.w;
            *(float4*)(outT + (size_t)atom * 640 + nb_base + 4 * tx) = r;
        }
    }
}

// ---------------- kernel P: per-pair main body --------------------------------
// warp handles PB=4 pairs; 8 warps/block; grid-stride over groups of 32 pairs
__global__ void __launch_bounds__(256, 4) k_pairs(
        const int* __restrict__ ind2,
        const float* __restrict__ basis,
        const float* __restrict__ d3,
        const float* __restrict__ fc_edge,
        const float* __restrict__ p3,
        const float* __restrict__ ii_W) {
    __shared__ float4 s_ii4[64 * 32];                      // 32 KB
    __shared__ __align__(16) float s_s[8][PB][64];         // 8 KB
    __shared__ float4 s_i1b[8][PB][16];                    // 8 KB

    int tid = threadIdx.x;
    int lane = tid & 31;
    int wid = tid >> 5;

    for (int t = tid; t < 64 * 32; t += 256)
        s_ii4[t] = __ldg(((const float4*)ii_W) + t);
    __syncthreads();

    const int NG = N_PAIRS / (8 * PB);
    for (int g = blockIdx.x; g < NG; g += gridDim.x) {
        int pbase = (g * 8 + wid) * PB;
        int ii_[PB], jj_[PB];

        // ---- phase A per pair: s = sum_b tanh(A[i]+B[j]) * basis
        #pragma unroll
        for (int pp = 0; pp < PB; pp++) {
            int p = pbase + pp;
            int2 ij = __ldg((const int2*)ind2 + p);
            ii_[pp] = ij.x; jj_[pp] = ij.y;
            const float2* basf = (const float2*)(basis + (size_t)p * 10);
            const float4* Ar = (const float4*)(g_A + (size_t)ij.x * 640);
            const float4* Br = (const float4*)(g_B + (size_t)ij.y * 640);
            float sum0 = 0.f, sum1 = 0.f;
            #pragma unroll
            for (int b2i = 0; b2i < 5; b2i++) {
                float4 a4 = __ldg(Ar + b2i * 32 + lane);
                float4 b4 = __ldg(Br + b2i * 32 + lane);
                float2 bb = __ldg(basf + b2i);
                float t0 = tanh_hw(a4.x + b4.x);
                float t1 = tanh_hw(a4.y + b4.y);
                float t2 = tanh_hw(a4.z + b4.z);
                float t3 = tanh_hw(a4.w + b4.w);
                sum0 = fmaf(t0, bb.x, sum0);
                sum0 = fmaf(t1, bb.y, sum0);
                sum1 = fmaf(t2, bb.x, sum1);
                sum1 = fmaf(t3, bb.y, sum1);
            }
            *(float2*)&s_s[wid][pp][2 * lane] = make_float2(sum0, sum1);
        }
        __syncwarp();

        // ---- phase B: i_pair = tanh(s @ ii_W), 4 pairs share each weight load
        float4 acc[PB];
        #pragma unroll
        for (int pp = 0; pp < PB; pp++) acc[pp] = make_float4(0.f, 0.f, 0.f, 0.f);
        #pragma unroll
        for (int c4 = 0; c4 < 16; c4++) {
            float4 w0 = s_ii4[(4 * c4 + 0) * 32 + lane];
            float4 w1 = s_ii4[(4 * c4 + 1) * 32 + lane];
            float4 w2 = s_ii4[(4 * c4 + 2) * 32 + lane];
            float4 w3 = s_ii4[(4 * c4 + 3) * 32 + lane];
            #pragma unroll
            for (int pp = 0; pp < PB; pp++) {
                float4 sv = ((const float4*)s_s[wid][pp])[c4];
                acc[pp].x = fmaf(sv.x, w0.x, acc[pp].x); acc[pp].y = fmaf(sv.x, w0.y, acc[pp].y);
                acc[pp].z = fmaf(sv.x, w0.z, acc[pp].z); acc[pp].w = fmaf(sv.x, w0.w, acc[pp].w);
                acc[pp].x = fmaf(sv.y, w1.x, acc[pp].x); acc[pp].y = fmaf(sv.y, w1.y, acc[pp].y);
                acc[pp].z = fmaf(sv.y, w1.z, acc[pp].z); acc[pp].w = fmaf(sv.y, w1.w, acc[pp].w);
                acc[pp].x = fmaf(sv.z, w2.x, acc[pp].x); acc[pp].y = fmaf(sv.z, w2.y, acc[pp].y);
                acc[pp].z = fmaf(sv.z, w2.z, acc[pp].z); acc[pp].w = fmaf(sv.z, w2.w, acc[pp].w);
                acc[pp].x = fmaf(sv.w, w3.x, acc[pp].x); acc[pp].y = fmaf(sv.w, w3.y, acc[pp].y);
                acc[pp].z = fmaf(sv.w, w3.z, acc[pp].z); acc[pp].w = fmaf(sv.w, w3.w, acc[pp].w);
            }
        }
        #pragma unroll
        for (int pp = 0; pp < PB; pp++) {
            float4 ip;
            ip.x = fast_tanh(acc[pp].x);
            ip.y = fast_tanh(acc[pp].y);
            ip.z = fast_tanh(acc[pp].z);
            ip.w = fast_tanh(acc[pp].w);
            red_add_v4(g_p1scat + (size_t)ii_[pp] * 128 + 4 * lane, ip);
            if (lane >= 16) s_i1b[wid][pp][lane - 16] = ip;
        }
        __syncwarp();

        // ---- phases C+D per pair
        #pragma unroll
        for (int pp = 0; pp < PB; pp++) {
            int p = pbase + pp;
            int i = ii_[pp], j = jj_[pp];
            float d0 = __ldg(&d3[3 * p + 0]);
            float d1 = __ldg(&d3[3 * p + 1]);
            float d2 = __ldg(&d3[3 * p + 2]);
            float fc = __ldg(&fc_edge[p]);
            float4 v4 = __ldg((const float4*)g_v + i);
            float proj = v4.x * d0 + v4.y * d1 + v4.z * d2;
            float wx = v4.x - proj * d0, wy = v4.y - proj * d1, wz = v4.z - proj * d2;
            float w2 = wx * wx + wy * wy + wz * wz;
            float g_deg = __fdividef(w2, w2 + 1e-4f);
            float rs = rsqrtf(w2 + 1e-6f);
            float tb = g_deg * fc * fc;
            float sc = rs * g_deg * tb;
            float term0 = d0 + wx * sc;
            float term1 = d1 + wy * sc;
            float term2 = d2 + wz * sc;

            const float4* p3j = (const float4*)(p3 + (size_t)j * 192);
            float* accBase = g_p3acc + (size_t)i * 192;
            #pragma unroll
            for (int it = 0; it < 2; it++) {
                int t = lane + 32 * it;
                if (t < 48) {
                    int x = t >> 4;
                    int m = t & 15;
                    float4 gg = s_i1b[wid][pp][m];
                    float4 pj = __ldg(&p3j[x * 16 + m]);
                    float tm = (x == 0) ? term0 : ((x == 1) ? term1 : term2);
                    float4 val;
                    val.x = gg.x * (pj.x + tm);
                    val.y = gg.y * (pj.y + tm);
                    val.z = gg.z * (pj.z + tm);
                    val.w = gg.w * (pj.w + tm);
                    red_add_v4(accBase + x * 64 + 4 * m, val);
                }
            }
        }
    }
}

// ---------------- kernel F: atom finalize (32 atoms/block, 8-atom reg block) --
__global__ void __launch_bounds__(256) k_final(
        const float* __restrict__ postW1,
        const float* __restrict__ postW2,
        const float* __restrict__ eqW,
        const float* __restrict__ q1W1,
        const float* __restrict__ q1b1,
        const float* __restrict__ q1W2,
        const float* __restrict__ q1b2,
        float* __restrict__ out) {
    __shared__ float s_cat[32][128];   // scat (phase1) then [p1_new | dotted]
    __shared__ float s_acc[32][192];   // p3acc tile
    __shared__ float s_b[32][64];      // t1 then h2a

    int tid = threadIdx.x;
    int o = tid & 63;
    int g = tid >> 6;          // 0..3, each handles 8 atoms
    int a_base = blockIdx.x * 32;
    float4 z4 = make_float4(0.f, 0.f, 0.f, 0.f);

    for (int e = tid; e < 32 * 32; e += 256) {
        int a = e >> 5, c4 = e & 31;
        int atom = a_base + a;
        ((float4*)s_cat[a])[c4] = (atom < N_ATOMS)
            ? __ldg((const float4*)(g_p1scat + (size_t)atom * 128) + c4) : z4;
    }
    for (int e = tid; e < 32 * 48; e += 256) {
        int a = e / 48, c4 = e % 48;
        int atom = a_base + a;
        ((float4*)s_acc[a])[c4] = (atom < N_ATOMS)
            ? __ldg((const float4*)(g_p3acc + (size_t)atom * 192) + c4) : z4;
    }
    __syncthreads();

    // phase1: t1 = tanh(scat @ postW1) -> s_b
    {
        float accv[8];
        #pragma unroll
        for (int u = 0; u < 8; u++) accv[u] = 0.f;
        for (int c = 0; c < 128; c++) {
            float w = __ldg(&postW1[c * 64 + o]);
            #pragma unroll
            for (int u = 0; u < 8; u++)
                accv[u] = fmaf(s_cat[8 * g + u][c], w, accv[u]);
        }
        __syncthreads();   // scat reads done before overwrite below
        #pragma unroll
        for (int u = 0; u < 8; u++) s_b[8 * g + u][o] = fast_tanh(accv[u]);
    }
    __syncthreads();

    // phase2: p1_new = tanh(t1 @ postW2) -> s_cat[:, 0:64]
    {
        float accv[8];
        #pragma unroll
        for (int u = 0; u < 8; u++) accv[u] = 0.f;
        for (int c = 0; c < 64; c++) {
            float w = __ldg(&postW2[c * 64 + o]);
            #pragma unroll
            for (int u = 0; u < 8; u++)
                accv[u] = fmaf(s_b[8 * g + u][c], w, accv[u]);
        }
        #pragma unroll
        for (int u = 0; u < 8; u++) s_cat[8 * g + u][o] = fast_tanh(accv[u]);
    }

    // phase3: p3n (regs) + dotted -> s_cat[:, 64:128]
    float p3n[3][8];
    #pragma unroll
    for (int x = 0; x < 3; x++) {
        float accv[8];
        #pragma unroll
        for (int u = 0; u < 8; u++) accv[u] = 0.f;
        for (int c = 0; c < 64; c++) {
            float w = __ldg(&eqW[c * 64 + o]);
            #pragma unroll
            for (int u = 0; u < 8; u++)
                accv[u] = fmaf(s_acc[8 * g + u][x * 64 + c], w, accv[u]);
        }
        #pragma unroll
        for (int u = 0; u < 8; u++) p3n[x][u] = accv[u];
    }
    #pragma unroll
    for (int u = 0; u < 8; u++)
        s_cat[8 * g + u][64 + o] = p3n[0][u] * p3n[0][u] +
                                   p3n[1][u] * p3n[1][u] +
                                   p3n[2][u] * p3n[2][u];
    __syncthreads();

    // phase4: h2a = tanh(cat @ q1W1 + b1) -> s_b
    {
        float accv[8];
        float bias = __ldg(&q1b1[o]);
        #pragma unroll
        for (int u = 0; u < 8; u++) accv[u] = bias;
        for (int c = 0; c < 128; c++) {
            float w = __ldg(&q1W1[c * 64 + o]);
            #pragma unroll
            for (int u = 0; u < 8; u++)
                accv[u] = fmaf(s_cat[8 * g + u][c], w, accv[u]);
        }
        __syncthreads();   // s_b(t1) reads done in phase2
        #pragma unroll
        for (int u = 0; u < 8; u++) s_b[8 * g + u][o] = fast_tanh(accv[u]);
    }
    __syncthreads();

    // phase5: h2 = tanh(h2a @ q1W2 + b2); write outputs
    {
        float h0[8], h1[8];
        float bias0 = __ldg(&q1b2[o]);
        float bias1 = __ldg(&q1b2[o + 64]);
        #pragma unroll
        for (int u = 0; u < 8; u++) { h0[u] = bias0; h1[u] = bias1; }
        for (int c = 0; c < 64; c++) {
            float w0 = __ldg(&q1W2[c * 128 + o]);
            float w1 = __ldg(&q1W2[c * 128 + o + 64]);
            #pragma unroll
            for (int u = 0; u < 8; u++) {
                float v = s_b[8 * g + u][c];
                h0[u] = fmaf(v, w0, h0[u]);
                h1[u] = fmaf(v, w1, h1[u]);
            }
        }
        #pragma unroll
        for (int u = 0; u < 8; u++) {
            int atom = a_base + 8 * g + u;
            if (atom < N_ATOMS) {
                float g1 = fast_tanh(h0[u]);
                float g3 = fast_tanh(h1[u]);
                out[(size_t)atom * 64 + o] = g1;
                float* o3 = out + (size_t)N_ATOMS * 64 + (size_t)atom * 192;
                #pragma unroll
                for (int x = 0; x < 3; x++)
                    o3[x * 64 + o] = p3n[x][u] * g3;
            }
        }
    }
}

// ---------------- launch ------------------------------------------------------
extern "C" void kernel_launch(void* const* d_in, const int* in_sizes, int n_in,
                              void* d_out, int out_size) {
    const int*   ind2    = (const int*)d_in[0];
    const float* p1      = (const float*)d_in[1];
    const float* p3      = (const float*)d_in[2];
    const float* basis   = (const float*)d_in[3];
    const float* d3      = (const float*)d_in[4];
    const float* fc_edge = (const float*)d_in[5];
    const float* ppreW1  = (const float*)d_in[6];
    const float* ppreb1  = (const float*)d_in[7];
    const float* ppreW2  = (const float*)d_in[8];
    const float* ppreb2  = (const float*)d_in[9];
    const float* piW     = (const float*)d_in[10];
    const float* pib     = (const float*)d_in[11];
    const float* iiW     = (const float*)d_in[12];
    const float* postW1  = (const float*)d_in[13];
    const float* postW2  = (const float*)d_in[14];
    const float* eqW     = (const float*)d_in[15];
    const float* q1W1    = (const float*)d_in[16];
    const float* q1b1    = (const float*)d_in[17];
    const float* q1W2    = (const float*)d_in[18];
    const float* q1b2    = (const float*)d_in[19];
    float* out = (float*)d_out;

    k_zero<<<512, 256>>>();
    k_vscat<<<(N_PAIRS + 255) / 256, 256>>>(ind2, d3, fc_edge);
    k_ab1<<<(N_ATOMS + 31) / 32, 256>>>(p1, ppreW1, ppreb1, ppreW2, ppreb2);
    {
        dim3 grid((N_ATOMS + 127) / 128, 20);
        k_ab2<<<grid, 256>>>(piW, pib);
    }
    k_pairs<<<592, 256>>>(ind2, basis, d3, fc_edge, p3, iiW);
    k_final<<<(N_ATOMS + 31) / 32, 256>>>(postW1, postW2, eqW, q1W1, q1b1, q1W2, q1b2, out);
}